// round 7
// baseline (speedup 1.0000x reference)
#include <cuda_runtime.h>
#include <cuda_bf16.h>
#include <math.h>
#include <stdint.h>

#define Bsz   4096
#define Nn    32
#define Hh    8
#define Dd    64
#define HIDd  512
#define MROWS (Bsz * Nn)
#define QKV_COLS (3 * HIDd)
#define Kdim  512

static const size_t OUT_ELEMS  = (size_t)MROWS * HIDd;
static const size_t ATTN_ELEMS = (size_t)Bsz * Hh * Nn * Nn;

__device__ float g_qkv[(size_t)MROWS * QKV_COLS];
__device__ __nv_bfloat16 g_Ahi[(size_t)MROWS * HIDd];
__device__ __nv_bfloat16 g_Alo[(size_t)MROWS * HIDd];
__device__ __nv_bfloat16 g_Whi[1048576 + 16];
__device__ __nv_bfloat16 g_Wlo[1048576 + 16];
__device__ float g_attn_fb[(size_t)Bsz * Hh * Nn * Nn];
__device__ unsigned int g_mask_bits[32];

#define WQKV_ELE (QKV_COLS * HIDd)

// ---------------- PTX helpers ----------------
__device__ __forceinline__ uint32_t smem_u32(const void* p) {
    uint32_t a;
    asm("{ .reg .u64 t; cvta.to.shared.u64 t, %1; cvt.u32.u64 %0, t; }"
        : "=r"(a) : "l"(p));
    return a;
}
__device__ __forceinline__ void cp16(uint32_t dst, const void* src) {
    asm volatile("cp.async.cg.shared.global [%0], [%1], 16;"
                 :: "r"(dst), "l"(src) : "memory");
}
#define CP_COMMIT() asm volatile("cp.async.commit_group;" ::: "memory")
#define CP_WAIT1()  asm volatile("cp.async.wait_group 1;" ::: "memory")
#define CP_WAIT0()  asm volatile("cp.async.wait_group 0;" ::: "memory")

#define LDSM4(r0, r1, r2, r3, addr) \
    asm volatile("ldmatrix.sync.aligned.m8n8.x4.shared.b16 {%0,%1,%2,%3}, [%4];" \
        : "=r"(r0), "=r"(r1), "=r"(r2), "=r"(r3) : "r"(addr))

#define MMA16816(c, a, b0, b1) \
    asm volatile("mma.sync.aligned.m16n8k16.row.col.f32.bf16.bf16.f32 " \
        "{%0,%1,%2,%3}, {%4,%5,%6,%7}, {%8,%9}, {%0,%1,%2,%3};" \
        : "+f"((c)[0]), "+f"((c)[1]), "+f"((c)[2]), "+f"((c)[3]) \
        : "r"((a)[0]), "r"((a)[1]), "r"((a)[2]), "r"((a)[3]), \
          "r"(b0), "r"(b1))

// ---------------- mask decode ----------------
__global__ void decode_mask_kernel(const unsigned char* __restrict__ raw) {
    __shared__ int onebyte;
    if (threadIdx.x == 0) {
        int ok = 1;
        for (int i = 0; i < 32; ++i) if (raw[33 * i] == 0) ok = 0;
        onebyte = ok;
    }
    __syncthreads();
    int i = threadIdx.x;
    unsigned int bits = 0;
    if (onebyte) {
        for (int j = 0; j < 32; ++j)
            if (raw[i * 32 + j] != 0) bits |= (1u << j);
    } else {
        const unsigned int* w = (const unsigned int*)raw;
        for (int j = 0; j < 32; ++j)
            if (w[i * 32 + j] != 0) bits |= (1u << j);
    }
    g_mask_bits[i] = bits;
}

// ---------------- fp32 -> bf16 hi/lo split ----------------
__global__ void __launch_bounds__(256)
split_kernel(const float* __restrict__ in, __nv_bfloat16* __restrict__ hi,
             __nv_bfloat16* __restrict__ lo, int n4)
{
    int i = blockIdx.x * 256 + threadIdx.x;
    if (i >= n4) return;
    float4 x = ((const float4*)in)[i];
    __nv_bfloat16 h0 = __float2bfloat16(x.x), h1 = __float2bfloat16(x.y);
    __nv_bfloat16 h2 = __float2bfloat16(x.z), h3 = __float2bfloat16(x.w);
    __nv_bfloat16 l0 = __float2bfloat16(x.x - __bfloat162float(h0));
    __nv_bfloat16 l1 = __float2bfloat16(x.y - __bfloat162float(h1));
    __nv_bfloat16 l2 = __float2bfloat16(x.z - __bfloat162float(h2));
    __nv_bfloat16 l3 = __float2bfloat16(x.w - __bfloat162float(h3));
    __nv_bfloat162 a; a.x = h0; a.y = h1;
    __nv_bfloat162 b; b.x = h2; b.y = h3;
    __nv_bfloat162 c; c.x = l0; c.y = l1;
    __nv_bfloat162 d; d.x = l2; d.y = l3;
    ((__nv_bfloat162*)hi)[2 * i + 0] = a;
    ((__nv_bfloat162*)hi)[2 * i + 1] = b;
    ((__nv_bfloat162*)lo)[2 * i + 0] = c;
    ((__nv_bfloat162*)lo)[2 * i + 1] = d;
}

// ---------------- mma.sync bf16 GEMM (NT), warp tile 64x64 ----------------
// C[m,n] = sum_k A[m,k]*B[n,k] + bias[n]; terms ah*bh + ah*bl + al*bh.
// CTA 128x128, 4 warps (2x2 of 64x64), KC=32, 2-stage cp.async.
#define GM  128
#define GN  128
#define GKC 32
#define NCHUNK (Kdim / GKC)       // 16
#define APITCH 80                 // 32 bf16 + 16B pad per smem row
#define MAT_BYTES (128 * APITCH)  // 10240
#define STAGE_BYTES (4 * MAT_BYTES)   // 40960
#define GEMM_SMEM (2 * STAGE_BYTES)   // 81920

__global__ void __launch_bounds__(128)
gemm_tc(const __nv_bfloat16* __restrict__ Ahi, const __nv_bfloat16* __restrict__ Alo,
        const __nv_bfloat16* __restrict__ Bhi, const __nv_bfloat16* __restrict__ Blo,
        const float* __restrict__ bias, float* __restrict__ C, int Nc)
{
    extern __shared__ char smem[];
    const uint32_t sb = smem_u32(smem);
    const int t = threadIdx.x, wid = t >> 5, lane = t & 31;
    const int bm = blockIdx.y * GM, bn = blockIdx.x * GN;
    const int wm = (wid & 1) * 64;     // warp M offset
    const int wn = (wid >> 1) * 64;    // warp N offset

    float acc[4][8][4];
#pragma unroll
    for (int i = 0; i < 4; ++i)
#pragma unroll
        for (int j = 0; j < 8; ++j)
#pragma unroll
            for (int q = 0; q < 4; ++q) acc[i][j][q] = 0.0f;

    auto load_stage = [&](int st, int k0) {
        uint32_t base = sb + st * (uint32_t)STAGE_BYTES;
#pragma unroll
        for (int it = 0; it < 4; ++it) {
            int idx = t + 128 * it;        // 0..511
            int r = idx >> 2, seg = idx & 3;
            uint32_t doff = (uint32_t)(r * APITCH + seg * 16);
            size_t soA = (size_t)(bm + r) * Kdim + k0 + seg * 8;
            size_t soB = (size_t)(bn + r) * Kdim + k0 + seg * 8;
            cp16(base + doff,                 Ahi + soA);
            cp16(base + MAT_BYTES + doff,     Alo + soA);
            cp16(base + 2 * MAT_BYTES + doff, Bhi + soB);
            cp16(base + 3 * MAT_BYTES + doff, Blo + soB);
        }
        CP_COMMIT();
    };

    load_stage(0, 0);

    const uint32_t lrow  = lane & 15;
    const uint32_t lcolb = (lane >> 4) * 16;

    for (int c = 0; c < NCHUNK; ++c) {
        if (c + 1 < NCHUNK) {
            load_stage((c + 1) & 1, (c + 1) * GKC);
            CP_WAIT1();
        } else {
            CP_WAIT0();
        }
        __syncthreads();

        uint32_t base = sb + (uint32_t)(c & 1) * STAGE_BYTES;
#pragma unroll
        for (int s = 0; s < 2; ++s) {
            uint32_t colb = s * 32 + lcolb;
            // A fragments: 4 m16 tiles, hi & lo
            uint32_t Ah[4][4], Al[4][4];
#pragma unroll
            for (int mi = 0; mi < 4; ++mi) {
                uint32_t ad = base + (wm + mi * 16 + lrow) * APITCH + colb;
                LDSM4(Ah[mi][0], Ah[mi][1], Ah[mi][2], Ah[mi][3], ad);
                LDSM4(Al[mi][0], Al[mi][1], Al[mi][2], Al[mi][3], ad + MAT_BYTES);
            }
#pragma unroll
            for (int ni = 0; ni < 4; ++ni) {
                uint32_t bd = base + 2 * MAT_BYTES
                            + (wn + ni * 16 + lrow) * APITCH + colb;
                uint32_t h0, h1, h2, h3, l0, l1, l2, l3;
                LDSM4(h0, h1, h2, h3, bd);
                LDSM4(l0, l1, l2, l3, bd + MAT_BYTES);
                // term-major: same-acc reuse distance = 8 MMAs
#pragma unroll
                for (int mi = 0; mi < 4; ++mi) {
                    MMA16816(acc[mi][2 * ni],     Ah[mi], h0, h2);
                    MMA16816(acc[mi][2 * ni + 1], Ah[mi], h1, h3);
                }
#pragma unroll
                for (int mi = 0; mi < 4; ++mi) {
                    MMA16816(acc[mi][2 * ni],     Ah[mi], l0, l2);
                    MMA16816(acc[mi][2 * ni + 1], Ah[mi], l1, l3);
                }
#pragma unroll
                for (int mi = 0; mi < 4; ++mi) {
                    MMA16816(acc[mi][2 * ni],     Al[mi], h0, h2);
                    MMA16816(acc[mi][2 * ni + 1], Al[mi], h1, h3);
                }
            }
        }
        __syncthreads();
    }

    // Epilogue
    const int row0 = bm + wm + (lane >> 2);
    const int col0 = bn + wn + (lane & 3) * 2;
#pragma unroll
    for (int mi = 0; mi < 4; ++mi) {
#pragma unroll
        for (int nj = 0; nj < 8; ++nj) {
            int r = row0 + mi * 16;
            int cc = col0 + nj * 8;
            float b0 = __ldg(&bias[cc]), b1 = __ldg(&bias[cc + 1]);
            float* p0 = C + (size_t)r * Nc + cc;
            float* p1 = C + (size_t)(r + 8) * Nc + cc;
            p0[0] = acc[mi][nj][0] + b0;
            p0[1] = acc[mi][nj][1] + b1;
            p1[0] = acc[mi][nj][2] + b0;
            p1[1] = acc[mi][nj][3] + b1;
        }
    }
}

// ---------------- attention (fused ctx hi/lo split) ----------------
__global__ void __launch_bounds__(128)
attn_kernel2(const float* __restrict__ qkv, __nv_bfloat16* __restrict__ chi,
             __nv_bfloat16* __restrict__ clo, float* __restrict__ attn_out)
{
    __shared__ float Qs[32][64];
    __shared__ float Ks[32][65];
    __shared__ float Vs[32][64];
    __shared__ float Ps[32][33];

    const int bh = blockIdx.x;
    const int b  = bh >> 3;
    const int h  = bh & 7;
    const int t  = threadIdx.x;
    const int wid = t >> 5, lane = t & 31;

    const float* base = qkv + (size_t)b * Nn * QKV_COLS + h * Dd;
#pragma unroll
    for (int r = 0; r < 4; ++r) {
        int idx = t + 128 * r;
        int i = idx >> 4, d4 = (idx & 15) * 4;
        size_t ro = (size_t)i * QKV_COLS + d4;
        float4 q = *(const float4*)&base[ro];
        float4 k = *(const float4*)&base[ro + HIDd];
        float4 v = *(const float4*)&base[ro + 2 * HIDd];
        *(float4*)&Qs[i][d4] = q;
        Ks[i][d4 + 0] = k.x; Ks[i][d4 + 1] = k.y;
        Ks[i][d4 + 2] = k.z; Ks[i][d4 + 3] = k.w;
        *(float4*)&Vs[i][d4] = v;
    }
    __syncthreads();

    {   // scores: warp wid owns rows [8w,8w+8), lane = column j
        const int j = lane;
        float a8[8];
#pragma unroll
        for (int r = 0; r < 8; ++r) a8[r] = 0.0f;
#pragma unroll 4
        for (int d = 0; d < 64; ++d) {
            float kv = Ks[j][d];
#pragma unroll
            for (int r = 0; r < 8; ++r)
                a8[r] += Qs[wid * 8 + r][d] * kv;
        }
        size_t abase = (size_t)bh * 1024;
#pragma unroll
        for (int r = 0; r < 8; ++r) {
            int i = wid * 8 + r;
            float s = ((g_mask_bits[i] >> j) & 1u) ? a8[r] * 0.125f : -1e9f;
            float mx = s;
#pragma unroll
            for (int o = 16; o; o >>= 1)
                mx = fmaxf(mx, __shfl_xor_sync(0xFFFFFFFFu, mx, o));
            float e = expf(s - mx);
            float sum = e;
#pragma unroll
            for (int o = 16; o; o >>= 1)
                sum += __shfl_xor_sync(0xFFFFFFFFu, sum, o);
            float pr = e / sum;
            Ps[i][j] = pr;
            attn_out[abase + (size_t)i * 32 + j] = pr;
        }
    }
    __syncthreads();

    {   // PV + fused hi/lo split of ctx
        const int d  = t & 63;
        const int hh = t >> 6;
        float a2[16];
#pragma unroll
        for (int r = 0; r < 16; ++r) a2[r] = 0.0f;
#pragma unroll 4
        for (int j = 0; j < 32; ++j) {
            float v = Vs[j][d];
#pragma unroll
            for (int r = 0; r < 16; ++r)
                a2[r] += Ps[hh * 16 + r][j] * v;
        }
        size_t cb = (size_t)b * Nn * HIDd + h * Dd + d;
#pragma unroll
        for (int r = 0; r < 16; ++r) {
            float v = a2[r];
            __nv_bfloat16 hv = __float2bfloat16(v);
            __nv_bfloat16 lv = __float2bfloat16(v - __bfloat162float(hv));
            size_t off = cb + (size_t)(hh * 16 + r) * HIDd;
            chi[off] = hv;
            clo[off] = lv;
        }
    }
}

// ---------------- launch ----------------
extern "C" void kernel_launch(void* const* d_in, const int* in_sizes, int n_in,
                              void* d_out, int out_size) {
    const float*         X    = (const float*)d_in[0];
    const unsigned char* mask = (const unsigned char*)d_in[1];
    const float*         Wqkv = (const float*)d_in[2];
    const float*         bqkv = (const float*)d_in[3];
    const float*         Wo   = (const float*)d_in[4];
    const float*         bo   = (const float*)d_in[5];

    float *qkv_p, *attn_fb_p;
    __nv_bfloat16 *ahi_p, *alo_p, *whi_p, *wlo_p;
    cudaGetSymbolAddress((void**)&qkv_p, g_qkv);
    cudaGetSymbolAddress((void**)&attn_fb_p, g_attn_fb);
    cudaGetSymbolAddress((void**)&ahi_p, g_Ahi);
    cudaGetSymbolAddress((void**)&alo_p, g_Alo);
    cudaGetSymbolAddress((void**)&whi_p, g_Whi);
    cudaGetSymbolAddress((void**)&wlo_p, g_Wlo);

    float* out = (float*)d_out;
    float *out_p, *attn_p;
    long long osz = (long long)out_size;
    if (osz >= (long long)(OUT_ELEMS + ATTN_ELEMS)) {
        out_p = out; attn_p = out + OUT_ELEMS;
    } else if (osz >= (long long)OUT_ELEMS) {
        out_p = out; attn_p = attn_fb_p;
    } else {
        attn_p = out; out_p = qkv_p;
    }

    cudaFuncSetAttribute(gemm_tc, cudaFuncAttributeMaxDynamicSharedMemorySize,
                         GEMM_SMEM);

    decode_mask_kernel<<<1, 32>>>(mask);

    // splits: X, Wqkv, Wo
    {
        int n4 = (MROWS * HIDd) / 4;
        split_kernel<<<(n4 + 255) / 256, 256>>>(X, ahi_p, alo_p, n4);
        int w4 = WQKV_ELE / 4;
        split_kernel<<<(w4 + 255) / 256, 256>>>(Wqkv, whi_p, wlo_p, w4);
        int o4 = (HIDd * HIDd) / 4;
        split_kernel<<<(o4 + 255) / 256, 256>>>(Wo, whi_p + WQKV_ELE,
                                                wlo_p + WQKV_ELE, o4);
    }

    // qkv = X @ Wqkv^T + bqkv   [131072 x 1536]
    gemm_tc<<<dim3(QKV_COLS / GN, MROWS / GM), 128, GEMM_SMEM>>>(
        ahi_p, alo_p, whi_p, wlo_p, bqkv, qkv_p, QKV_COLS);

    // attention (writes ctx hi/lo directly into g_Ahi/g_Alo)
    attn_kernel2<<<Bsz * Hh, 128>>>(qkv_p, ahi_p, alo_p, attn_p);

    // out = ctx @ Wo^T + bo     [131072 x 512]
    gemm_tc<<<dim3(HIDd / GN, MROWS / GM), 128, GEMM_SMEM>>>(
        ahi_p, alo_p, whi_p + WQKV_ELE, wlo_p + WQKV_ELE, bo, out_p, HIDd);
}

// round 8
// speedup vs baseline: 1.4188x; 1.4188x over previous
#include <cuda_runtime.h>
#include <cuda_fp16.h>
#include <math.h>
#include <stdint.h>

#define Bsz   4096
#define Nn    32
#define Hh    8
#define Dd    64
#define HIDd  512
#define MROWS (Bsz * Nn)
#define QKV_COLS (3 * HIDd)
#define Kdim  512

static const size_t OUT_ELEMS  = (size_t)MROWS * HIDd;
static const size_t ATTN_ELEMS = (size_t)Bsz * Hh * Nn * Nn;

__device__ float g_qkv[(size_t)MROWS * QKV_COLS];
__device__ __half g_Ahi[(size_t)MROWS * HIDd];
__device__ __half g_Whi[1048576 + 16];
__device__ __half g_Wlo[1048576 + 16];
__device__ float g_attn_fb[(size_t)Bsz * Hh * Nn * Nn];
__device__ unsigned int g_mask_bits[32];

#define WQKV_ELE (QKV_COLS * HIDd)

// ---------------- PTX helpers ----------------
__device__ __forceinline__ uint32_t smem_u32(const void* p) {
    uint32_t a;
    asm("{ .reg .u64 t; cvta.to.shared.u64 t, %1; cvt.u32.u64 %0, t; }"
        : "=r"(a) : "l"(p));
    return a;
}
__device__ __forceinline__ void cp16(uint32_t dst, const void* src) {
    asm volatile("cp.async.cg.shared.global [%0], [%1], 16;"
                 :: "r"(dst), "l"(src) : "memory");
}
#define CP_COMMIT() asm volatile("cp.async.commit_group;" ::: "memory")
#define CP_WAIT1()  asm volatile("cp.async.wait_group 1;" ::: "memory")
#define CP_WAIT0()  asm volatile("cp.async.wait_group 0;" ::: "memory")

#define LDSM4(r0, r1, r2, r3, addr) \
    asm volatile("ldmatrix.sync.aligned.m8n8.x4.shared.b16 {%0,%1,%2,%3}, [%4];" \
        : "=r"(r0), "=r"(r1), "=r"(r2), "=r"(r3) : "r"(addr))

#define MMA16816(c, a, b0, b1) \
    asm volatile("mma.sync.aligned.m16n8k16.row.col.f32.f16.f16.f32 " \
        "{%0,%1,%2,%3}, {%4,%5,%6,%7}, {%8,%9}, {%0,%1,%2,%3};" \
        : "+f"((c)[0]), "+f"((c)[1]), "+f"((c)[2]), "+f"((c)[3]) \
        : "r"((a)[0]), "r"((a)[1]), "r"((a)[2]), "r"((a)[3]), \
          "r"(b0), "r"(b1))

// ---------------- mask decode ----------------
__global__ void decode_mask_kernel(const unsigned char* __restrict__ raw) {
    __shared__ int onebyte;
    if (threadIdx.x == 0) {
        int ok = 1;
        for (int i = 0; i < 32; ++i) if (raw[33 * i] == 0) ok = 0;
        onebyte = ok;
    }
    __syncthreads();
    int i = threadIdx.x;
    unsigned int bits = 0;
    if (onebyte) {
        for (int j = 0; j < 32; ++j)
            if (raw[i * 32 + j] != 0) bits |= (1u << j);
    } else {
        const unsigned int* w = (const unsigned int*)raw;
        for (int j = 0; j < 32; ++j)
            if (w[i * 32 + j] != 0) bits |= (1u << j);
    }
    g_mask_bits[i] = bits;
}

// ---------------- fp32 -> fp16 splits ----------------
__global__ void __launch_bounds__(256)
split_hi_kernel(const float* __restrict__ in, __half* __restrict__ hi, int n4)
{
    int i = blockIdx.x * 256 + threadIdx.x;
    if (i >= n4) return;
    float4 x = ((const float4*)in)[i];
    __half2 h0; h0.x = __float2half_rn(x.x); h0.y = __float2half_rn(x.y);
    __half2 h1; h1.x = __float2half_rn(x.z); h1.y = __float2half_rn(x.w);
    ((__half2*)hi)[2 * i + 0] = h0;
    ((__half2*)hi)[2 * i + 1] = h1;
}

__global__ void __launch_bounds__(256)
split_hilo_kernel(const float* __restrict__ in, __half* __restrict__ hi,
                  __half* __restrict__ lo, int n4)
{
    int i = blockIdx.x * 256 + threadIdx.x;
    if (i >= n4) return;
    float4 x = ((const float4*)in)[i];
    __half a0 = __float2half_rn(x.x), a1 = __float2half_rn(x.y);
    __half a2 = __float2half_rn(x.z), a3 = __float2half_rn(x.w);
    __half b0 = __float2half_rn(x.x - __half2float(a0));
    __half b1 = __float2half_rn(x.y - __half2float(a1));
    __half b2 = __float2half_rn(x.z - __half2float(a2));
    __half b3 = __float2half_rn(x.w - __half2float(a3));
    __half2 h0; h0.x = a0; h0.y = a1;
    __half2 h1; h1.x = a2; h1.y = a3;
    __half2 l0; l0.x = b0; l0.y = b1;
    __half2 l1; l1.x = b2; l1.y = b3;
    ((__half2*)hi)[2 * i + 0] = h0;
    ((__half2*)hi)[2 * i + 1] = h1;
    ((__half2*)lo)[2 * i + 0] = l0;
    ((__half2*)lo)[2 * i + 1] = l1;
}

// ---------------- mma.sync fp16 GEMM (NT) ----------------
// C[m,n] = sum_k A[m,k]*B[n,k] + bias[n];  C = Ah*(Bh+Bl), 2 terms.
// CTA 128x128, 8 warps (warp tile 32x64), KC=32, 2-stage cp.async.
#define GM  128
#define GN  128
#define GKC 32
#define NCHUNK (Kdim / GKC)       // 16
#define APITCH 80                 // 32 fp16 + 16B pad per smem row
#define MAT_BYTES (128 * APITCH)  // 10240
#define STAGE_BYTES (3 * MAT_BYTES)   // Ah|Bh|Bl = 30720
#define GEMM_SMEM (2 * STAGE_BYTES)   // 61440

__global__ void __launch_bounds__(256, 2)
gemm_tc(const __half* __restrict__ Ahi, const __half* __restrict__ Bhi,
        const __half* __restrict__ Blo, const float* __restrict__ bias,
        float* __restrict__ C, int Nc)
{
    extern __shared__ char smem[];
    const uint32_t sb = smem_u32(smem);
    const int t = threadIdx.x, wid = t >> 5, lane = t & 31;
    const int bm = blockIdx.y * GM, bn = blockIdx.x * GN;
    const int wm = (wid & 3) * 32;     // warp M offset
    const int wn = (wid >> 2) * 64;    // warp N offset

    float acc[2][8][4];
#pragma unroll
    for (int i = 0; i < 2; ++i)
#pragma unroll
        for (int j = 0; j < 8; ++j)
#pragma unroll
            for (int q = 0; q < 4; ++q) acc[i][j][q] = 0.0f;

    auto load_stage = [&](int st, int k0) {
        uint32_t base = sb + st * (uint32_t)STAGE_BYTES;
#pragma unroll
        for (int it = 0; it < 2; ++it) {
            int idx = t + 256 * it;        // 0..511
            int r = idx >> 2, seg = idx & 3;
            uint32_t doff = (uint32_t)(r * APITCH + seg * 16);
            size_t soA = (size_t)(bm + r) * Kdim + k0 + seg * 8;
            size_t soB = (size_t)(bn + r) * Kdim + k0 + seg * 8;
            cp16(base + doff,                 Ahi + soA);
            cp16(base + MAT_BYTES + doff,     Bhi + soB);
            cp16(base + 2 * MAT_BYTES + doff, Blo + soB);
        }
        CP_COMMIT();
    };

    load_stage(0, 0);

    const uint32_t lrow  = lane & 15;
    const uint32_t lcolb = (lane >> 4) * 16;

    for (int c = 0; c < NCHUNK; ++c) {
        if (c + 1 < NCHUNK) {
            load_stage((c + 1) & 1, (c + 1) * GKC);
            CP_WAIT1();
        } else {
            CP_WAIT0();
        }
        __syncthreads();

        uint32_t base = sb + (uint32_t)(c & 1) * STAGE_BYTES;
#pragma unroll
        for (int s = 0; s < 2; ++s) {
            uint32_t colb = s * 32 + lcolb;
            uint32_t Ah[2][4];
#pragma unroll
            for (int mi = 0; mi < 2; ++mi) {
                uint32_t ad = base + (wm + mi * 16 + lrow) * APITCH + colb;
                LDSM4(Ah[mi][0], Ah[mi][1], Ah[mi][2], Ah[mi][3], ad);
            }
#pragma unroll
            for (int ni = 0; ni < 4; ++ni) {
                uint32_t bd = base + MAT_BYTES
                            + (wn + ni * 16 + lrow) * APITCH + colb;
                uint32_t h0, h1, h2, h3, l0, l1, l2, l3;
                LDSM4(h0, h1, h2, h3, bd);
                LDSM4(l0, l1, l2, l3, bd + MAT_BYTES);
#pragma unroll
                for (int mi = 0; mi < 2; ++mi) {
                    MMA16816(acc[mi][2 * ni],     Ah[mi], h0, h2);
                    MMA16816(acc[mi][2 * ni + 1], Ah[mi], h1, h3);
                }
#pragma unroll
                for (int mi = 0; mi < 2; ++mi) {
                    MMA16816(acc[mi][2 * ni],     Ah[mi], l0, l2);
                    MMA16816(acc[mi][2 * ni + 1], Ah[mi], l1, l3);
                }
            }
        }
        __syncthreads();
    }

    // Epilogue
    const int row0 = bm + wm + (lane >> 2);
    const int col0 = bn + wn + (lane & 3) * 2;
#pragma unroll
    for (int mi = 0; mi < 2; ++mi) {
#pragma unroll
        for (int nj = 0; nj < 8; ++nj) {
            int r = row0 + mi * 16;
            int cc = col0 + nj * 8;
            float b0 = __ldg(&bias[cc]), b1 = __ldg(&bias[cc + 1]);
            float* p0 = C + (size_t)r * Nc + cc;
            float* p1 = C + (size_t)(r + 8) * Nc + cc;
            p0[0] = acc[mi][nj][0] + b0;
            p0[1] = acc[mi][nj][1] + b1;
            p1[0] = acc[mi][nj][2] + b0;
            p1[1] = acc[mi][nj][3] + b1;
        }
    }
}

// ---------------- attention (fused ctx -> fp16 hi) ----------------
__global__ void __launch_bounds__(128)
attn_kernel2(const float* __restrict__ qkv, __half* __restrict__ chi,
             float* __restrict__ attn_out)
{
    __shared__ float Qs[32][64];
    __shared__ float Ks[32][65];
    __shared__ float Vs[32][64];
    __shared__ float Ps[32][33];

    const int bh = blockIdx.x;
    const int b  = bh >> 3;
    const int h  = bh & 7;
    const int t  = threadIdx.x;
    const int wid = t >> 5, lane = t & 31;

    const float* base = qkv + (size_t)b * Nn * QKV_COLS + h * Dd;
#pragma unroll
    for (int r = 0; r < 4; ++r) {
        int idx = t + 128 * r;
        int i = idx >> 4, d4 = (idx & 15) * 4;
        size_t ro = (size_t)i * QKV_COLS + d4;
        float4 q = *(const float4*)&base[ro];
        float4 k = *(const float4*)&base[ro + HIDd];
        float4 v = *(const float4*)&base[ro + 2 * HIDd];
        *(float4*)&Qs[i][d4] = q;
        Ks[i][d4 + 0] = k.x; Ks[i][d4 + 1] = k.y;
        Ks[i][d4 + 2] = k.z; Ks[i][d4 + 3] = k.w;
        *(float4*)&Vs[i][d4] = v;
    }
    __syncthreads();

    {   // scores: warp wid owns rows [8w,8w+8), lane = column j
        const int j = lane;
        float a8[8];
#pragma unroll
        for (int r = 0; r < 8; ++r) a8[r] = 0.0f;
#pragma unroll 4
        for (int d = 0; d < 64; ++d) {
            float kv = Ks[j][d];
#pragma unroll
            for (int r = 0; r < 8; ++r)
                a8[r] += Qs[wid * 8 + r][d] * kv;
        }
        size_t abase = (size_t)bh * 1024;
#pragma unroll
        for (int r = 0; r < 8; ++r) {
            int i = wid * 8 + r;
            float s = ((g_mask_bits[i] >> j) & 1u) ? a8[r] * 0.125f : -1e9f;
            float mx = s;
#pragma unroll
            for (int o = 16; o; o >>= 1)
                mx = fmaxf(mx, __shfl_xor_sync(0xFFFFFFFFu, mx, o));
            float e = expf(s - mx);
            float sum = e;
#pragma unroll
            for (int o = 16; o; o >>= 1)
                sum += __shfl_xor_sync(0xFFFFFFFFu, sum, o);
            float pr = e / sum;
            Ps[i][j] = pr;
            attn_out[abase + (size_t)i * 32 + j] = pr;
        }
    }
    __syncthreads();

    {   // PV + fused fp16 conversion of ctx
        const int d  = t & 63;
        const int hh = t >> 6;
        float a2[16];
#pragma unroll
        for (int r = 0; r < 16; ++r) a2[r] = 0.0f;
#pragma unroll 4
        for (int j = 0; j < 32; ++j) {
            float v = Vs[j][d];
#pragma unroll
            for (int r = 0; r < 16; ++r)
                a2[r] += Ps[hh * 16 + r][j] * v;
        }
        size_t cb = (size_t)b * Nn * HIDd + h * Dd + d;
#pragma unroll
        for (int r = 0; r < 16; ++r)
            chi[cb + (size_t)(hh * 16 + r) * HIDd] = __float2half_rn(a2[r]);
    }
}

// ---------------- launch ----------------
extern "C" void kernel_launch(void* const* d_in, const int* in_sizes, int n_in,
                              void* d_out, int out_size) {
    const float*         X    = (const float*)d_in[0];
    const unsigned char* mask = (const unsigned char*)d_in[1];
    const float*         Wqkv = (const float*)d_in[2];
    const float*         bqkv = (const float*)d_in[3];
    const float*         Wo   = (const float*)d_in[4];
    const float*         bo   = (const float*)d_in[5];

    float *qkv_p, *attn_fb_p;
    __half *ahi_p, *whi_p, *wlo_p;
    cudaGetSymbolAddress((void**)&qkv_p, g_qkv);
    cudaGetSymbolAddress((void**)&attn_fb_p, g_attn_fb);
    cudaGetSymbolAddress((void**)&ahi_p, g_Ahi);
    cudaGetSymbolAddress((void**)&whi_p, g_Whi);
    cudaGetSymbolAddress((void**)&wlo_p, g_Wlo);

    float* out = (float*)d_out;
    float *out_p, *attn_p;
    long long osz = (long long)out_size;
    if (osz >= (long long)(OUT_ELEMS + ATTN_ELEMS)) {
        out_p = out; attn_p = out + OUT_ELEMS;
    } else if (osz >= (long long)OUT_ELEMS) {
        out_p = out; attn_p = attn_fb_p;
    } else {
        attn_p = out; out_p = qkv_p;
    }

    cudaFuncSetAttribute(gemm_tc, cudaFuncAttributeMaxDynamicSharedMemorySize,
                         GEMM_SMEM);

    decode_mask_kernel<<<1, 32>>>(mask);

    // splits: X (hi only), Wqkv (hi+lo), Wo (hi+lo)
    {
        int n4 = (MROWS * HIDd) / 4;
        split_hi_kernel<<<(n4 + 255) / 256, 256>>>(X, ahi_p, n4);
        int w4 = WQKV_ELE / 4;
        split_hilo_kernel<<<(w4 + 255) / 256, 256>>>(Wqkv, whi_p, wlo_p, w4);
        int o4 = (HIDd * HIDd) / 4;
        split_hilo_kernel<<<(o4 + 255) / 256, 256>>>(Wo, whi_p + WQKV_ELE,
                                                     wlo_p + WQKV_ELE, o4);
    }

    // qkv = X @ Wqkv^T + bqkv   [131072 x 1536]
    gemm_tc<<<dim3(QKV_COLS / GN, MROWS / GM), 256, GEMM_SMEM>>>(
        ahi_p, whi_p, wlo_p, bqkv, qkv_p, QKV_COLS);

    // attention (writes ctx fp16 hi into g_Ahi)
    attn_kernel2<<<Bsz * Hh, 128>>>(qkv_p, ahi_p, attn_p);

    // out = ctx @ Wo^T + bo     [131072 x 512]
    gemm_tc<<<dim3(HIDd / GN, MROWS / GM), 256, GEMM_SMEM>>>(
        ahi_p, whi_p + WQKV_ELE, wlo_p + WQKV_ELE, bo, out_p, HIDd);
}

// round 9
// speedup vs baseline: 1.9468x; 1.3722x over previous
#include <cuda_runtime.h>
#include <cuda_fp16.h>
#include <math.h>
#include <stdint.h>

#define Bsz   4096
#define Nn    32
#define Hh    8
#define Dd    64
#define HIDd  512
#define MROWS (Bsz * Nn)
#define QKV_COLS (3 * HIDd)
#define Kdim  512

static const size_t OUT_ELEMS  = (size_t)MROWS * HIDd;
static const size_t ATTN_ELEMS = (size_t)Bsz * Hh * Nn * Nn;

__device__ float g_qkv[(size_t)MROWS * QKV_COLS];
__device__ __half g_Ahi[(size_t)MROWS * HIDd];
__device__ __half g_Whi[1048576 + 16];
__device__ float g_attn_fb[(size_t)Bsz * Hh * Nn * Nn];
__device__ unsigned int g_mask_bits[32];

#define WQKV_ELE (QKV_COLS * HIDd)

// ---------------- PTX helpers ----------------
__device__ __forceinline__ uint32_t smem_u32(const void* p) {
    uint32_t a;
    asm("{ .reg .u64 t; cvta.to.shared.u64 t, %1; cvt.u32.u64 %0, t; }"
        : "=r"(a) : "l"(p));
    return a;
}
__device__ __forceinline__ void cp16(uint32_t dst, const void* src) {
    asm volatile("cp.async.cg.shared.global [%0], [%1], 16;"
                 :: "r"(dst), "l"(src) : "memory");
}
#define CP_COMMIT() asm volatile("cp.async.commit_group;" ::: "memory")
#define CP_WAIT1()  asm volatile("cp.async.wait_group 1;" ::: "memory")
#define CP_WAIT0()  asm volatile("cp.async.wait_group 0;" ::: "memory")

#define LDSM4(r0, r1, r2, r3, addr) \
    asm volatile("ldmatrix.sync.aligned.m8n8.x4.shared.b16 {%0,%1,%2,%3}, [%4];" \
        : "=r"(r0), "=r"(r1), "=r"(r2), "=r"(r3) : "r"(addr))

#define MMA16816(c, a, b0, b1) \
    asm volatile("mma.sync.aligned.m16n8k16.row.col.f32.f16.f16.f32 " \
        "{%0,%1,%2,%3}, {%4,%5,%6,%7}, {%8,%9}, {%0,%1,%2,%3};" \
        : "+f"((c)[0]), "+f"((c)[1]), "+f"((c)[2]), "+f"((c)[3]) \
        : "r"((a)[0]), "r"((a)[1]), "r"((a)[2]), "r"((a)[3]), \
          "r"(b0), "r"(b1))

// ---------------- mask decode ----------------
__global__ void decode_mask_kernel(const unsigned char* __restrict__ raw) {
    __shared__ int onebyte;
    if (threadIdx.x == 0) {
        int ok = 1;
        for (int i = 0; i < 32; ++i) if (raw[33 * i] == 0) ok = 0;
        onebyte = ok;
    }
    __syncthreads();
    int i = threadIdx.x;
    unsigned int bits = 0;
    if (onebyte) {
        for (int j = 0; j < 32; ++j)
            if (raw[i * 32 + j] != 0) bits |= (1u << j);
    } else {
        const unsigned int* w = (const unsigned int*)raw;
        for (int j = 0; j < 32; ++j)
            if (w[i * 32 + j] != 0) bits |= (1u << j);
    }
    g_mask_bits[i] = bits;
}

// ---------------- fp32 -> fp16 convert ----------------
__global__ void __launch_bounds__(256)
split_hi_kernel(const float* __restrict__ in, __half* __restrict__ hi, int n4)
{
    int i = blockIdx.x * 256 + threadIdx.x;
    if (i >= n4) return;
    float4 x = ((const float4*)in)[i];
    __half2 h0; h0.x = __float2half_rn(x.x); h0.y = __float2half_rn(x.y);
    __half2 h1; h1.x = __float2half_rn(x.z); h1.y = __float2half_rn(x.w);
    ((__half2*)hi)[2 * i + 0] = h0;
    ((__half2*)hi)[2 * i + 1] = h1;
}

// ---------------- mma.sync fp16 GEMM (NT), single term ----------------
// C[m,n] = sum_k A[m,k]*B[n,k] + bias[n].
// CTA 128x128, 8 warps (warp tile 32x64), KC=32, 2-stage cp.async.
#define GM  128
#define GN  128
#define GKC 32
#define NCHUNK (Kdim / GKC)       // 16
#define APITCH 80                 // 32 fp16 + 16B pad per smem row
#define MAT_BYTES (128 * APITCH)  // 10240
#define STAGE_BYTES (2 * MAT_BYTES)   // Ah|Bh = 20480
#define GEMM_SMEM (2 * STAGE_BYTES)   // 40960

__global__ void __launch_bounds__(256, 2)
gemm_tc(const __half* __restrict__ Ahi, const __half* __restrict__ Bhi,
        const float* __restrict__ bias, float* __restrict__ C, int Nc)
{
    extern __shared__ char smem[];
    const uint32_t sb = smem_u32(smem);
    const int t = threadIdx.x, wid = t >> 5, lane = t & 31;
    const int bm = blockIdx.y * GM, bn = blockIdx.x * GN;
    const int wm = (wid & 3) * 32;     // warp M offset
    const int wn = (wid >> 2) * 64;    // warp N offset

    float acc[2][8][4];
#pragma unroll
    for (int i = 0; i < 2; ++i)
#pragma unroll
        for (int j = 0; j < 8; ++j)
#pragma unroll
            for (int q = 0; q < 4; ++q) acc[i][j][q] = 0.0f;

    auto load_stage = [&](int st, int k0) {
        uint32_t base = sb + st * (uint32_t)STAGE_BYTES;
#pragma unroll
        for (int it = 0; it < 2; ++it) {
            int idx = t + 256 * it;        // 0..511
            int r = idx >> 2, seg = idx & 3;
            uint32_t doff = (uint32_t)(r * APITCH + seg * 16);
            size_t soA = (size_t)(bm + r) * Kdim + k0 + seg * 8;
            size_t soB = (size_t)(bn + r) * Kdim + k0 + seg * 8;
            cp16(base + doff,             Ahi + soA);
            cp16(base + MAT_BYTES + doff, Bhi + soB);
        }
        CP_COMMIT();
    };

    load_stage(0, 0);

    const uint32_t lrow  = lane & 15;
    const uint32_t lcolb = (lane >> 4) * 16;

    for (int c = 0; c < NCHUNK; ++c) {
        if (c + 1 < NCHUNK) {
            load_stage((c + 1) & 1, (c + 1) * GKC);
            CP_WAIT1();
        } else {
            CP_WAIT0();
        }
        __syncthreads();

        uint32_t base = sb + (uint32_t)(c & 1) * STAGE_BYTES;
#pragma unroll
        for (int s = 0; s < 2; ++s) {
            uint32_t colb = s * 32 + lcolb;
            uint32_t Ah[2][4];
#pragma unroll
            for (int mi = 0; mi < 2; ++mi) {
                uint32_t ad = base + (wm + mi * 16 + lrow) * APITCH + colb;
                LDSM4(Ah[mi][0], Ah[mi][1], Ah[mi][2], Ah[mi][3], ad);
            }
#pragma unroll
            for (int ni = 0; ni < 4; ++ni) {
                uint32_t bd = base + MAT_BYTES
                            + (wn + ni * 16 + lrow) * APITCH + colb;
                uint32_t h0, h1, h2, h3;
                LDSM4(h0, h1, h2, h3, bd);
#pragma unroll
                for (int mi = 0; mi < 2; ++mi) {
                    MMA16816(acc[mi][2 * ni],     Ah[mi], h0, h2);
                    MMA16816(acc[mi][2 * ni + 1], Ah[mi], h1, h3);
                }
            }
        }
        __syncthreads();
    }

    // Epilogue
    const int row0 = bm + wm + (lane >> 2);
    const int col0 = bn + wn + (lane & 3) * 2;
#pragma unroll
    for (int mi = 0; mi < 2; ++mi) {
#pragma unroll
        for (int nj = 0; nj < 8; ++nj) {
            int r = row0 + mi * 16;
            int cc = col0 + nj * 8;
            float b0 = __ldg(&bias[cc]), b1 = __ldg(&bias[cc + 1]);
            float* p0 = C + (size_t)r * Nc + cc;
            float* p1 = C + (size_t)(r + 8) * Nc + cc;
            p0[0] = acc[mi][nj][0] + b0;
            p0[1] = acc[mi][nj][1] + b1;
            p1[0] = acc[mi][nj][2] + b0;
            p1[1] = acc[mi][nj][3] + b1;
        }
    }
}

// ---------------- attention (fused ctx -> fp16) ----------------
__global__ void __launch_bounds__(128)
attn_kernel2(const float* __restrict__ qkv, __half* __restrict__ chi,
             float* __restrict__ attn_out)
{
    __shared__ float Qs[32][64];
    __shared__ float Ks[32][65];
    __shared__ float Vs[32][64];
    __shared__ float Ps[32][33];

    const int bh = blockIdx.x;
    const int b  = bh >> 3;
    const int h  = bh & 7;
    const int t  = threadIdx.x;
    const int wid = t >> 5, lane = t & 31;

    const float* base = qkv + (size_t)b * Nn * QKV_COLS + h * Dd;
#pragma unroll
    for (int r = 0; r < 4; ++r) {
        int idx = t + 128 * r;
        int i = idx >> 4, d4 = (idx & 15) * 4;
        size_t ro = (size_t)i * QKV_COLS + d4;
        float4 q = *(const float4*)&base[ro];
        float4 k = *(const float4*)&base[ro + HIDd];
        float4 v = *(const float4*)&base[ro + 2 * HIDd];
        *(float4*)&Qs[i][d4] = q;
        Ks[i][d4 + 0] = k.x; Ks[i][d4 + 1] = k.y;
        Ks[i][d4 + 2] = k.z; Ks[i][d4 + 3] = k.w;
        *(float4*)&Vs[i][d4] = v;
    }
    __syncthreads();

    {   // scores: warp wid owns rows [8w,8w+8), lane = column j
        const int j = lane;
        float a8[8];
#pragma unroll
        for (int r = 0; r < 8; ++r) a8[r] = 0.0f;
#pragma unroll 4
        for (int d = 0; d < 64; ++d) {
            float kv = Ks[j][d];
#pragma unroll
            for (int r = 0; r < 8; ++r)
                a8[r] += Qs[wid * 8 + r][d] * kv;
        }
        size_t abase = (size_t)bh * 1024;
#pragma unroll
        for (int r = 0; r < 8; ++r) {
            int i = wid * 8 + r;
            float s = ((g_mask_bits[i] >> j) & 1u) ? a8[r] * 0.125f : -1e9f;
            float mx = s;
#pragma unroll
            for (int o = 16; o; o >>= 1)
                mx = fmaxf(mx, __shfl_xor_sync(0xFFFFFFFFu, mx, o));
            float e = expf(s - mx);
            float sum = e;
#pragma unroll
            for (int o = 16; o; o >>= 1)
                sum += __shfl_xor_sync(0xFFFFFFFFu, sum, o);
            float pr = e / sum;
            Ps[i][j] = pr;
            attn_out[abase + (size_t)i * 32 + j] = pr;
        }
    }
    __syncthreads();

    {   // PV + fused fp16 conversion of ctx
        const int d  = t & 63;
        const int hh = t >> 6;
        float a2[16];
#pragma unroll
        for (int r = 0; r < 16; ++r) a2[r] = 0.0f;
#pragma unroll 4
        for (int j = 0; j < 32; ++j) {
            float v = Vs[j][d];
#pragma unroll
            for (int r = 0; r < 16; ++r)
                a2[r] += Ps[hh * 16 + r][j] * v;
        }
        size_t cb = (size_t)b * Nn * HIDd + h * Dd + d;
#pragma unroll
        for (int r = 0; r < 16; ++r)
            chi[cb + (size_t)(hh * 16 + r) * HIDd] = __float2half_rn(a2[r]);
    }
}

// ---------------- launch ----------------
extern "C" void kernel_launch(void* const* d_in, const int* in_sizes, int n_in,
                              void* d_out, int out_size) {
    const float*         X    = (const float*)d_in[0];
    const unsigned char* mask = (const unsigned char*)d_in[1];
    const float*         Wqkv = (const float*)d_in[2];
    const float*         bqkv = (const float*)d_in[3];
    const float*         Wo   = (const float*)d_in[4];
    const float*         bo   = (const float*)d_in[5];

    float *qkv_p, *attn_fb_p;
    __half *ahi_p, *whi_p;
    cudaGetSymbolAddress((void**)&qkv_p, g_qkv);
    cudaGetSymbolAddress((void**)&attn_fb_p, g_attn_fb);
    cudaGetSymbolAddress((void**)&ahi_p, g_Ahi);
    cudaGetSymbolAddress((void**)&whi_p, g_Whi);

    float* out = (float*)d_out;
    float *out_p, *attn_p;
    long long osz = (long long)out_size;
    if (osz >= (long long)(OUT_ELEMS + ATTN_ELEMS)) {
        out_p = out; attn_p = out + OUT_ELEMS;
    } else if (osz >= (long long)OUT_ELEMS) {
        out_p = out; attn_p = attn_fb_p;
    } else {
        attn_p = out; out_p = qkv_p;
    }

    cudaFuncSetAttribute(gemm_tc, cudaFuncAttributeMaxDynamicSharedMemorySize,
                         GEMM_SMEM);

    decode_mask_kernel<<<1, 32>>>(mask);

    // converts: X, Wqkv, Wo -> fp16
    {
        int n4 = (MROWS * HIDd) / 4;
        split_hi_kernel<<<(n4 + 255) / 256, 256>>>(X, ahi_p, n4);
        int w4 = WQKV_ELE / 4;
        split_hi_kernel<<<(w4 + 255) / 256, 256>>>(Wqkv, whi_p, w4);
        int o4 = (HIDd * HIDd) / 4;
        split_hi_kernel<<<(o4 + 255) / 256, 256>>>(Wo, whi_p + WQKV_ELE, o4);
    }

    // qkv = X @ Wqkv^T + bqkv   [131072 x 1536]
    gemm_tc<<<dim3(QKV_COLS / GN, MROWS / GM), 256, GEMM_SMEM>>>(
        ahi_p, whi_p, bqkv, qkv_p, QKV_COLS);

    // attention (writes ctx fp16 into g_Ahi)
    attn_kernel2<<<Bsz * Hh, 128>>>(qkv_p, ahi_p, attn_p);

    // out = ctx @ Wo^T + bo     [131072 x 512]
    gemm_tc<<<dim3(HIDd / GN, MROWS / GM), 256, GEMM_SMEM>>>(
        ahi_p, whi_p + WQKV_ELE, bo, out_p, HIDd);
}